// round 17
// baseline (speedup 1.0000x reference)
#include <cuda_runtime.h>
#include <cuda_bf16.h>
#include <cstdint>

// FusionMarkovGNN — algebraically collapsed, all GEMMs on mma.sync (HMMA),
// 5 graph nodes. Layer tile 64x64 (grid 256 blocks -> 2 CTAs/SM).
//   W_eff[n,l] = conv_w[l] @ mss[n] = wsum_l @ relu(adj_n) + rare exact
//   corrections (dense sign-pattern flags, applied inside weff_mma).
//   Per layer: y = relu(BN(W_eff[n,l] @ x + conv_b)).
// bf16 3-term split (hi*hi + hi*lo + lo*hi), fp32 accum, m16n8k16.
// Device globals referenced ONLY in device code (host-side refs are UB).

#define CC 256
#define SS 16
#define HW 1024
#define NB 4

typedef unsigned long long u64;
typedef uint32_t u32;

__device__ u32           g_wspack[3 * CC * CC];   // [l][o][a] packed split of wsum
__device__ u32           g_apack[NB * CC * CC];   // [n][b][a] packed split of relu(adj^T)
__device__ float         g_weff[NB * 3 * CC * CC];// [n][l][o][b]
__device__ u32           g_xpack[2][NB * HW * CC];// [buf][n][p][b]: (lo16<<16)|hi16
__device__ unsigned char g_flag[NB * SS * CC];    // dense: 0=relu,1=full,2=zero

// ---------------------------------------------------------------- helpers
__device__ __forceinline__ u32 smem_u32(const void* p) {
    u32 a;
    asm("{ .reg .u64 t; cvta.to.shared.u64 t, %1; cvt.u32.u64 %0, t; }" : "=r"(a) : "l"(p));
    return a;
}
__device__ __forceinline__ u32 pk2(float lo, float hi) {
    u32 r; asm("cvt.rn.bf16x2.f32 %0, %1, %2;" : "=r"(r) : "f"(hi), "f"(lo)); return r;
}
__device__ __forceinline__ void splt(float x, float& h, float& l) {
    __nv_bfloat16 bh = __float2bfloat16(x);
    h = __bfloat162float(bh);
    l = x - h;
}
__device__ __forceinline__ u32 packsplit(float y) {
    __nv_bfloat16 bh = __float2bfloat16(y);
    float hf = __bfloat162float(bh);
    __nv_bfloat16 bl = __float2bfloat16(y - hf);
    return ((u32)__bfloat16_as_ushort(bl) << 16) | (u32)__bfloat16_as_ushort(bh);
}
__device__ __forceinline__ void ldm4(u32& r0, u32& r1, u32& r2, u32& r3, u32 addr) {
    asm volatile("ldmatrix.sync.aligned.m8n8.x4.shared.b16 {%0,%1,%2,%3}, [%4];"
                 : "=r"(r0), "=r"(r1), "=r"(r2), "=r"(r3) : "r"(addr));
}
__device__ __forceinline__ void mma16816(float* c, const u32* a, const u32* b) {
    asm volatile(
        "mma.sync.aligned.m16n8k16.row.col.f32.bf16.bf16.f32 "
        "{%0,%1,%2,%3}, {%4,%5,%6,%7}, {%8,%9}, {%0,%1,%2,%3};"
        : "+f"(c[0]), "+f"(c[1]), "+f"(c[2]), "+f"(c[3])
        : "r"(a[0]), "r"(a[1]), "r"(a[2]), "r"(a[3]), "r"(b[0]), "r"(b[1]));
}

// ---------------------------------------------------------------- mega prep
// One kernel, 2112 blocks of 256 threads, dispatched on blockIdx.x:
//  [0,768):     wsum   -> g_wspack
//  [768,832):   detect -> g_flag (dense overwrite; deterministic)
//  [832,1088):  adjprep-> g_apack
//  [1088,2112): prep   -> g_xpack[0]
__global__ __launch_bounds__(256) void mega_prep(
    const float* __restrict__ feats,
    const float* __restrict__ adj,
    const float* __restrict__ w) {
    __shared__ float t[32][33];
    int bx = blockIdx.x;
    int tid = threadIdx.x;

    if (bx < 768) {
        int idx = bx * 256 + tid;
        int l  = idx >> 16;
        int oa = idx & 0xFFFF;
        int o = oa >> 8, a = oa & 255;
        const float* base = w + (size_t)l * CC * SS * CC + (size_t)o * (SS * CC) + a;
        float s = 0.0f;
#pragma unroll
        for (int k = 0; k < 16; k++) s += base[k * CC];
        g_wspack[idx] = packsplit(s);
    } else if (bx < 832) {
        int di = bx - 768;
        int n = di & 3, k = di >> 2;
        int b = tid;
        const float* m = adj + (size_t)n * CC * CC;
        bool anyp = false, allp = true;
#pragma unroll
        for (int i = 0; i < 16; i++) {
            float v = m[(size_t)(k * 16 + i) * CC + b];
            anyp = anyp || (v > 0.0f);
            allp = allp && (v > 0.0f);
        }
        g_flag[(n * SS + k) * CC + b] = allp ? 1 : (anyp ? 0 : 2);
    } else if (bx < 1088) {
        int ai = bx - 832;
        int n = ai >> 6, rem = ai & 63;
        int a0 = (rem >> 3) * 32, b0 = (rem & 7) * 32;
        int tx = tid & 31, ty = tid >> 5;
        const float* m = adj + (size_t)n * CC * CC;
#pragma unroll
        for (int i = 0; i < 4; i++) {
            int a = ty + i * 8;
            t[a][tx] = m[(size_t)(a0 + a) * CC + b0 + tx];
        }
        __syncthreads();
        u32* ap = g_apack + (size_t)n * CC * CC;
#pragma unroll
        for (int i = 0; i < 4; i++) {
            int b = ty + i * 8;
            ap[(size_t)(b0 + b) * CC + a0 + tx] = packsplit(fmaxf(t[tx][b], 0.0f));
        }
    } else {
        int pi = bx - 1088;
        int n = pi >> 8, rem = pi & 255;
        int p0 = (rem >> 3) * 32, b0 = (rem & 7) * 32;
        int tx = tid & 31, ty = tid >> 5;
        const float* f = feats + ((size_t)n * CC + b0) * HW + p0;
#pragma unroll
        for (int i = 0; i < 4; i++) {
            int b = ty + i * 8;
            t[b][tx] = f[(size_t)b * HW + tx];
        }
        __syncthreads();
        u32* xp = g_xpack[0] + ((size_t)n * HW + p0) * CC + b0;
#pragma unroll
        for (int i = 0; i < 4; i++) {
            int p = ty + i * 8;
            xp[(size_t)p * CC + tx] = packsplit(t[tx][p]);
        }
    }
}

// ---------------------------------------------------------------- weff smem layout
#define S_XHI 0
#define S_XLO 10240
#define S_WHI 20480
#define S_WLO 25600
#define S_TOT (33792 + 512)

// ---------------------------------------------------------------- weff via mma
// C[o][b] = wsum_l[o][a] @ relu(adj_n)^T[b][a]. Tile 128(o) x 64(b), K=256.
// Post-GEMM: exact corrections for full/zero flag columns (this block's
// output region only — disjoint across blocks, so plain global RMW is safe).
__global__ __launch_bounds__(256) void weff_mma(
    const float* __restrict__ adj, const float* __restrict__ convw) {
    __shared__ __align__(16) unsigned char sraw[S_TOT];
    __shared__ u32 clist[1024];
    __shared__ int ccnt;
    u32 sb = smem_u32(sraw);
    int tid = threadIdx.x;
    int wid = tid >> 5, lane = tid & 31;
    int wm = wid >> 1, wn = wid & 1;
    int m0 = wm * 32, n0 = wn * 32;

    int nl = blockIdx.z;
    int l = nl % 3, n = nl / 3;
    int o0 = blockIdx.x * 128;
    int b0 = blockIdx.y * 64;
    const u32* Ap = g_wspack + (size_t)l * CC * CC + (size_t)o0 * CC;
    const u32* Bp = g_apack  + (size_t)n * CC * CC + (size_t)b0 * CC;
    float* Cc = g_weff + (size_t)nl * CC * CC;

    int la = lane & 15, lb = (lane >> 4) & 1;
    int brr = (lane & 7) + ((lane & 16) ? 8 : 0);
    int bhalf = (lane >> 3) & 1;

    float acc[2][4][4] = {};

    int xp_p[4], xp_u[4];
#pragma unroll
    for (int i = 0; i < 4; i++) { int idx = tid + 256 * i; xp_p[i] = idx >> 3; xp_u[i] = idx & 7; }
    int wo[2], wu[2];
#pragma unroll
    for (int i = 0; i < 2; i++) { int idx = tid + 256 * i; wo[i] = idx >> 3; wu[i] = idx & 7; }

    uint4 gx[4], gw[2];
#pragma unroll
    for (int i = 0; i < 4; i++)
        gx[i] = *(const uint4*)(Ap + (size_t)xp_p[i] * CC + xp_u[i] * 4);
#pragma unroll
    for (int i = 0; i < 2; i++)
        gw[i] = *(const uint4*)(Bp + (size_t)wo[i] * CC + wu[i] * 4);

    for (int kc = 0; kc < 8; kc++) {
#pragma unroll
        for (int i = 0; i < 4; i++) {
            u32 v0 = gx[i].x, v1 = gx[i].y, v2 = gx[i].z, v3 = gx[i].w;
            *(uint2*)(sraw + S_XHI + xp_p[i] * 80 + xp_u[i] * 8) =
                make_uint2((v0 & 0xFFFFu) | (v1 << 16), (v2 & 0xFFFFu) | (v3 << 16));
            *(uint2*)(sraw + S_XLO + xp_p[i] * 80 + xp_u[i] * 8) =
                make_uint2((v0 >> 16) | (v1 & 0xFFFF0000u), (v2 >> 16) | (v3 & 0xFFFF0000u));
        }
#pragma unroll
        for (int i = 0; i < 2; i++) {
            u32 v0 = gw[i].x, v1 = gw[i].y, v2 = gw[i].z, v3 = gw[i].w;
            *(uint2*)(sraw + S_WHI + wo[i] * 80 + wu[i] * 8) =
                make_uint2((v0 & 0xFFFFu) | (v1 << 16), (v2 & 0xFFFFu) | (v3 << 16));
            *(uint2*)(sraw + S_WLO + wo[i] * 80 + wu[i] * 8) =
                make_uint2((v0 >> 16) | (v1 & 0xFFFF0000u), (v2 >> 16) | (v3 & 0xFFFF0000u));
        }
        __syncthreads();

        if (kc < 7) {
            int a0 = (kc + 1) * 32;
#pragma unroll
            for (int i = 0; i < 4; i++)
                gx[i] = *(const uint4*)(Ap + (size_t)xp_p[i] * CC + a0 + xp_u[i] * 4);
#pragma unroll
            for (int i = 0; i < 2; i++)
                gw[i] = *(const uint4*)(Bp + (size_t)wo[i] * CC + a0 + wu[i] * 4);
        }

#pragma unroll
        for (int ks = 0; ks < 2; ks++) {
            u32 ahi[2][4], alo[2][4];
#pragma unroll
            for (int mi = 0; mi < 2; mi++) {
                u32 off = (u32)((m0 + mi * 16 + la) * 80 + ks * 32 + lb * 16);
                ldm4(ahi[mi][0], ahi[mi][1], ahi[mi][2], ahi[mi][3], sb + S_XHI + off);
                ldm4(alo[mi][0], alo[mi][1], alo[mi][2], alo[mi][3], sb + S_XLO + off);
            }
            u32 bh[4][2], bl[4][2];
#pragma unroll
            for (int g = 0; g < 2; g++) {
                u32 off = (u32)((n0 + g * 16 + brr) * 80 + ks * 32 + bhalf * 16);
                u32 r0, r1, r2, r3;
                ldm4(r0, r1, r2, r3, sb + S_WHI + off);
                bh[g * 2][0] = r0; bh[g * 2][1] = r1;
                bh[g * 2 + 1][0] = r2; bh[g * 2 + 1][1] = r3;
                ldm4(r0, r1, r2, r3, sb + S_WLO + off);
                bl[g * 2][0] = r0; bl[g * 2][1] = r1;
                bl[g * 2 + 1][0] = r2; bl[g * 2 + 1][1] = r3;
            }
#pragma unroll
            for (int mi = 0; mi < 2; mi++)
#pragma unroll
                for (int ni = 0; ni < 4; ni++) {
                    mma16816(acc[mi][ni], ahi[mi], bh[ni]);
                    mma16816(acc[mi][ni], ahi[mi], bl[ni]);
                    mma16816(acc[mi][ni], alo[mi], bh[ni]);
                }
        }
        __syncthreads();
    }

    int pr = lane >> 2, oc = (lane & 3) * 2;
#pragma unroll
    for (int mi = 0; mi < 2; mi++)
#pragma unroll
        for (int ni = 0; ni < 4; ni++) {
            int o = o0 + m0 + mi * 16 + pr;
            int b = b0 + n0 + ni * 8 + oc;
            *(float2*)(Cc + (size_t)o * CC + b) =
                make_float2(acc[mi][ni][0], acc[mi][ni][1]);
            *(float2*)(Cc + (size_t)(o + 8) * CC + b) =
                make_float2(acc[mi][ni][2], acc[mi][ni][3]);
        }

    // ---- corrections (rare): scan dense flags for (n, all k, our b range)
    if (tid == 0) ccnt = 0;
    __syncthreads();
    for (int i = tid; i < SS * 64; i += 256) {
        int k = i >> 6, bb = b0 + (i & 63);
        unsigned char st = g_flag[(n * SS + k) * CC + bb];
        if (st) { int idx = atomicAdd(&ccnt, 1); clist[idx] = (u32)((k << 10) | (bb << 2) | st); }
    }
    __syncthreads();
    int cnt = ccnt;
    for (int e = 0; e < cnt; e++) {
        u32 ent = clist[e];
        int k = ent >> 10, bb = (ent >> 2) & 0xFF, st = ent & 3;
        if (tid < 128) {
            int o = o0 + tid;
            const float* wrow = convw + (size_t)l * CC * SS * CC + (size_t)o * (SS * CC) + k * CC;
            const float* m = adj + (size_t)n * CC * CC;
            float s = 0.0f;
            if (st == 1) {
                for (int a = 0; a < CC; a++) s = fmaf(wrow[a], fminf(m[(size_t)a * CC + bb], 0.0f), s);
            } else {
                for (int a = 0; a < CC; a++) s = fmaf(-wrow[a], fmaxf(m[(size_t)a * CC + bb], 0.0f), s);
            }
            Cc[(size_t)o * CC + bb] += s;
        }
    }
}

// ---------------------------------------------------------------- layer smem layout
#define L_XHI 0
#define L_XLO 5120
#define L_WHI 10240
#define L_WLO 15360
#define L_DS  0
#define L_CSC 20480
#define L_CAD (20480 + 256)
#define L_TOT (20480 + 512)

// ---------------------------------------------------------------- mma.sync layer
// Block tile: 64 (p) x 64 (o), K = 256 in 8 chunks of 32. 256 threads,
// 8 warps as 2(m=p) x 4(n=o), warp tile 32x16. Grid (16, 4, 4) = 256 CTAs.
template <int IN_BUF, int OUT_BUF>
__global__ __launch_bounds__(256) void layer_mma(
    float* __restrict__ Y,
    int l,
    const float* __restrict__ cb_, const float* __restrict__ gamma_,
    const float* __restrict__ beta_, const float* __restrict__ mean_,
    const float* __restrict__ var_) {
    __shared__ __align__(16) unsigned char sraw[L_TOT];
    u32 sb = smem_u32(sraw);
    int tid = threadIdx.x;
    int wid = tid >> 5, lane = tid & 31;
    int wm = wid >> 2, wn = wid & 3;
    int m0 = wm * 32, n0 = wn * 16;

    int n = blockIdx.z;
    int pcol0 = blockIdx.x * 64;
    int o0 = blockIdx.y * 64;
    const u32* Xp = g_xpack[IN_BUF] + ((size_t)n * HW + pcol0) * CC;
    const float* Wp = g_weff + (size_t)(n * 3 + l) * CC * CC + (size_t)o0 * CC;

    int la = lane & 15, lb = (lane >> 4) & 1;
    int brr = (lane & 7) + ((lane & 16) ? 8 : 0);
    int bhalf = (lane >> 3) & 1;

    float acc[2][2][4] = {};

    // staging: 64 rows x 8 16B-units for X (uint4 of packed u32) and W (float4)
    int sp_r[2], sp_u[2];
#pragma unroll
    for (int i = 0; i < 2; i++) { int idx = tid + 256 * i; sp_r[i] = idx >> 3; sp_u[i] = idx & 7; }

    uint4 gx[2];
    float4 gw[2];
#pragma unroll
    for (int i = 0; i < 2; i++) {
        gx[i] = *(const uint4*)(Xp + (size_t)sp_r[i] * CC + sp_u[i] * 4);
        gw[i] = *(const float4*)(Wp + (size_t)sp_r[i] * CC + sp_u[i] * 4);
    }

    for (int kc = 0; kc < 8; kc++) {
#pragma unroll
        for (int i = 0; i < 2; i++) {
            u32 v0 = gx[i].x, v1 = gx[i].y, v2 = gx[i].z, v3 = gx[i].w;
            *(uint2*)(sraw + L_XHI + sp_r[i] * 80 + sp_u[i] * 8) =
                make_uint2((v0 & 0xFFFFu) | (v1 << 16), (v2 & 0xFFFFu) | (v3 << 16));
            *(uint2*)(sraw + L_XLO + sp_r[i] * 80 + sp_u[i] * 8) =
                make_uint2((v0 >> 16) | (v1 & 0xFFFF0000u), (v2 >> 16) | (v3 & 0xFFFF0000u));
            float h0, h1, h2, h3, l0, l1, l2, l3;
            splt(gw[i].x, h0, l0); splt(gw[i].y, h1, l1);
            splt(gw[i].z, h2, l2); splt(gw[i].w, h3, l3);
            *(uint2*)(sraw + L_WHI + sp_r[i] * 80 + sp_u[i] * 8) = make_uint2(pk2(h0, h1), pk2(h2, h3));
            *(uint2*)(sraw + L_WLO + sp_r[i] * 80 + sp_u[i] * 8) = make_uint2(pk2(l0, l1), pk2(l2, l3));
        }
        __syncthreads();

        if (kc < 7) {
            int b0 = (kc + 1) * 32;
#pragma unroll
            for (int i = 0; i < 2; i++) {
                gx[i] = *(const uint4*)(Xp + (size_t)sp_r[i] * CC + b0 + sp_u[i] * 4);
                gw[i] = *(const float4*)(Wp + (size_t)sp_r[i] * CC + b0 + sp_u[i] * 4);
            }
        }

#pragma unroll
        for (int ks = 0; ks < 2; ks++) {
            u32 ahi[2][4], alo[2][4];
#pragma unroll
            for (int mi = 0; mi < 2; mi++) {
                u32 off = (u32)((m0 + mi * 16 + la) * 80 + ks * 32 + lb * 16);
                ldm4(ahi[mi][0], ahi[mi][1], ahi[mi][2], ahi[mi][3], sb + L_XHI + off);
                ldm4(alo[mi][0], alo[mi][1], alo[mi][2], alo[mi][3], sb + L_XLO + off);
            }
            u32 bh[2][2], bl[2][2];
            {
                u32 off = (u32)((n0 + brr) * 80 + ks * 32 + bhalf * 16);
                u32 r0, r1, r2, r3;
                ldm4(r0, r1, r2, r3, sb + L_WHI + off);
                bh[0][0] = r0; bh[0][1] = r1; bh[1][0] = r2; bh[1][1] = r3;
                ldm4(r0, r1, r2, r3, sb + L_WLO + off);
                bl[0][0] = r0; bl[0][1] = r1; bl[1][0] = r2; bl[1][1] = r3;
            }
#pragma unroll
            for (int mi = 0; mi < 2; mi++)
#pragma unroll
                for (int ni = 0; ni < 2; ni++) {
                    mma16816(acc[mi][ni], ahi[mi], bh[ni]);
                    mma16816(acc[mi][ni], ahi[mi], bl[ni]);
                    mma16816(acc[mi][ni], alo[mi], bh[ni]);
                }
        }
        __syncthreads();
    }

    // ---- epilogue: stage C^T through smem, BN+ReLU, coalesced stores
    float* Ds  = (float*)(sraw + L_DS);
    float* csc = (float*)(sraw + L_CSC);
    float* cad = (float*)(sraw + L_CAD);
    if (tid < 64) {
        int o = o0 + tid;
        float sc = gamma_[o] * rsqrtf(var_[o] + 1e-5f);
        csc[tid] = sc;
        cad[tid] = (cb_[o] - mean_[o]) * sc + beta_[o];
    }
    int pr = lane >> 2, oc = (lane & 3) * 2;
#pragma unroll
    for (int mi = 0; mi < 2; mi++)
#pragma unroll
        for (int ni = 0; ni < 2; ni++) {
            int p = m0 + mi * 16 + pr;
            int o = n0 + ni * 8 + oc;
            *(float2*)&Ds[p * 66 + o]       = make_float2(acc[mi][ni][0], acc[mi][ni][1]);
            *(float2*)&Ds[(p + 8) * 66 + o] = make_float2(acc[mi][ni][2], acc[mi][ni][3]);
        }
    __syncthreads();

    float* Yn = Y + (size_t)n * CC * HW;
    for (int idx = tid; idx < 64 * 64; idx += 256) {
        int o = idx >> 6, p = idx & 63;
        float v = fmaxf(fmaf(Ds[p * 66 + o], csc[o], cad[o]), 0.0f);
        Yn[(size_t)(o0 + o) * HW + pcol0 + p] = v;
    }
    if (OUT_BUF >= 0) {
        u32* Xo = g_xpack[OUT_BUF < 0 ? 0 : OUT_BUF] + ((size_t)n * HW + pcol0) * CC + o0;
        for (int idx = tid; idx < 64 * 64; idx += 256) {
            int p = idx >> 6, o = idx & 63;
            float v = fmaxf(fmaf(Ds[p * 66 + o], csc[o], cad[o]), 0.0f);
            Xo[(size_t)p * CC + o] = packsplit(v);
        }
    }
}

// ---------------------------------------------------------------- launch
extern "C" void kernel_launch(void* const* d_in, const int* in_sizes, int n_in,
                              void* d_out, int out_size) {
    (void)in_sizes; (void)n_in; (void)out_size;
    const float* feats = (const float*)d_in[0];  // [4,256,32,32]
    const float* adj   = (const float*)d_in[1];  // [4,256,256]
    const float* convw = (const float*)d_in[2];  // [3,256,4096]
    const float* convb = (const float*)d_in[3];  // [3,256]
    const float* gamma = (const float*)d_in[4];
    const float* beta  = (const float*)d_in[5];
    const float* mean  = (const float*)d_in[6];
    const float* var   = (const float*)d_in[7];
    float* out = (float*)d_out;                  // [3,4,256,32,32]

    mega_prep<<<2112, 256>>>(feats, adj, convw);
    weff_mma<<<dim3(2, 4, NB * 3), 256>>>(adj, convw);

    const size_t SEC = (size_t)NB * CC * HW;
    dim3 grid(HW / 64, CC / 64, NB);
    layer_mma<0, 1><<<grid, 256>>>(
        out, 0,
        convb + 0 * CC, gamma + 0 * CC, beta + 0 * CC, mean + 0 * CC, var + 0 * CC);
    layer_mma<1, 0><<<grid, 256>>>(
        out + SEC, 1,
        convb + 1 * CC, gamma + 1 * CC, beta + 1 * CC, mean + 1 * CC, var + 1 * CC);
    layer_mma<0, -1><<<grid, 256>>>(
        out + 2 * SEC, 2,
        convb + 2 * CC, gamma + 2 * CC, beta + 2 * CC, mean + 2 * CC, var + 2 * CC);
}